// round 3
// baseline (speedup 1.0000x reference)
#include <cuda_runtime.h>
#include <math.h>

#define NMAX 50000
#define EMAX 800000
#define C 128

// ---------------- scratch (static __device__, no allocation) ----------------
__device__ int   g_cnt [NMAX];
__device__ int   g_fill[NMAX];
__device__ int   g_ptr [NMAX + 1];
__device__ int   g_ecol[EMAX];
__device__ float g_norm[NMAX];
__device__ float g_aggc[NMAX * C];
__device__ float g_agge[NMAX * C];
__device__ float g_x1  [NMAX * C];
__device__ float g_x2  [NMAX * C];

// ---------------- CSR build ----------------
__global__ void zero_cnt_kernel(int N) {
    int i = blockIdx.x * blockDim.x + threadIdx.x;
    if (i < N) g_cnt[i] = 0;
}

__global__ void hist_kernel(const int* __restrict__ row, int E) {
    int i = blockIdx.x * blockDim.x + threadIdx.x;
    if (i < E) atomicAdd(&g_cnt[row[i]], 1);
}

__global__ void scan_kernel(int N) {
    __shared__ int sums[1024];
    int t = threadIdx.x;
    int chunk = (N + 1023) >> 10;
    int start = t * chunk;
    int end = min(start + chunk, N);
    int s = 0;
    for (int i = start; i < end; i++) s += g_cnt[i];
    sums[t] = s;
    __syncthreads();
    for (int off = 1; off < 1024; off <<= 1) {
        int v = (t >= off) ? sums[t - off] : 0;
        __syncthreads();
        sums[t] += v;
        __syncthreads();
    }
    int base = sums[t] - s;  // exclusive prefix of this thread's chunk
    for (int i = start; i < end; i++) {
        g_ptr[i]  = base;
        g_fill[i] = base;
        base += g_cnt[i];
    }
    if (t == 0) g_ptr[N] = sums[1023];
}

__global__ void fill_kernel(const int* __restrict__ row, const int* __restrict__ col, int E) {
    int i = blockIdx.x * blockDim.x + threadIdx.x;
    if (i < E) {
        int r = row[i];
        int p = atomicAdd(&g_fill[r], 1);
        g_ecol[p] = col[i];
    }
}

// ---------------- per-node L2 norms ----------------
__global__ void norm_kernel(const float* __restrict__ X, int N) {
    int node = blockIdx.x * 8 + (threadIdx.x >> 5);
    int lane = threadIdx.x & 31;
    if (node >= N) return;
    float4 v = ((const float4*)X)[node * 32 + lane];
    float s = v.x * v.x + v.y * v.y + v.z * v.z + v.w * v.w;
    #pragma unroll
    for (int o = 16; o; o >>= 1) s += __shfl_xor_sync(0xffffffffu, s, o);
    if (lane == 0) g_norm[node] = sqrtf(s);
}

// ---------------- edge pass 1: cos + eud on x, fused gather-aggregate ----------------
__global__ void edge1_kernel(const float* __restrict__ X, int N) {
    int node = blockIdx.x * 8 + (threadIdx.x >> 5);
    int lane = threadIdx.x & 31;
    if (node >= N) return;
    const float4* X4 = (const float4*)X;
    float4 xi = X4[node * 32 + lane];
    float ni = g_norm[node];
    int s = g_ptr[node], e = g_ptr[node + 1];
    float4 ac = make_float4(0.f, 0.f, 0.f, 0.f);
    float4 ae = make_float4(0.f, 0.f, 0.f, 0.f);
    for (int j = s; j < e; j++) {
        int c = g_ecol[j];
        float4 xc = __ldg(&X4[c * 32 + lane]);
        float nc = __ldg(&g_norm[c]);
        float d = xi.x * xc.x + xi.y * xc.y + xi.z * xc.z + xi.w * xc.w;
        float ux = xi.x - xc.x + 1e-6f;
        float uy = xi.y - xc.y + 1e-6f;
        float uz = xi.z - xc.z + 1e-6f;
        float uw = xi.w - xc.w + 1e-6f;
        float u = ux * ux + uy * uy + uz * uz + uw * uw;
        #pragma unroll
        for (int o = 16; o; o >>= 1) {
            d += __shfl_xor_sync(0xffffffffu, d, o);
            u += __shfl_xor_sync(0xffffffffu, u, o);
        }
        float ecos = d / fmaxf(ni * nc, 1e-8f);
        float eeud = sqrtf(u);
        ac.x += ecos * xc.x; ac.y += ecos * xc.y; ac.z += ecos * xc.z; ac.w += ecos * xc.w;
        ae.x += eeud * xc.x; ae.y += eeud * xc.y; ae.z += eeud * xc.z; ae.w += eeud * xc.w;
    }
    float inv = 1.0f / fmaxf((float)(e - s), 1.0f);
    ac.x *= inv; ac.y *= inv; ac.z *= inv; ac.w *= inv;
    ae.x *= inv; ae.y *= inv; ae.z *= inv; ae.w *= inv;
    ((float4*)g_aggc)[node * 32 + lane] = ac;
    ((float4*)g_agge)[node * 32 + lane] = ae;
}

// ---------------- edge pass 2: cos on x3, eud on x4 ----------------
__global__ void edge2_kernel(const float* __restrict__ X3, const float* __restrict__ X4, int N) {
    int node = blockIdx.x * 8 + (threadIdx.x >> 5);
    int lane = threadIdx.x & 31;
    if (node >= N) return;
    const float4* A4 = (const float4*)X3;
    const float4* B4 = (const float4*)X4;
    float4 x3i = A4[node * 32 + lane];
    float4 x4i = B4[node * 32 + lane];
    float n3 = g_norm[node];  // norms of x3
    int s = g_ptr[node], e = g_ptr[node + 1];
    float4 ac = make_float4(0.f, 0.f, 0.f, 0.f);
    float4 ae = make_float4(0.f, 0.f, 0.f, 0.f);
    for (int j = s; j < e; j++) {
        int c = g_ecol[j];
        float4 xc3 = __ldg(&A4[c * 32 + lane]);
        float4 xc4 = __ldg(&B4[c * 32 + lane]);
        float nc = __ldg(&g_norm[c]);
        float d = x3i.x * xc3.x + x3i.y * xc3.y + x3i.z * xc3.z + x3i.w * xc3.w;
        float ux = x4i.x - xc4.x + 1e-6f;
        float uy = x4i.y - xc4.y + 1e-6f;
        float uz = x4i.z - xc4.z + 1e-6f;
        float uw = x4i.w - xc4.w + 1e-6f;
        float u = ux * ux + uy * uy + uz * uz + uw * uw;
        #pragma unroll
        for (int o = 16; o; o >>= 1) {
            d += __shfl_xor_sync(0xffffffffu, d, o);
            u += __shfl_xor_sync(0xffffffffu, u, o);
        }
        float ecos = d / fmaxf(n3 * nc, 1e-8f);
        float eeud = sqrtf(u);
        ac.x += ecos * xc3.x; ac.y += ecos * xc3.y; ac.z += ecos * xc3.z; ac.w += ecos * xc3.w;
        ae.x += eeud * xc4.x; ae.y += eeud * xc4.y; ae.z += eeud * xc4.z; ae.w += eeud * xc4.w;
    }
    float inv = 1.0f / fmaxf((float)(e - s), 1.0f);
    ac.x *= inv; ac.y *= inv; ac.z *= inv; ac.w *= inv;
    ae.x *= inv; ae.y *= inv; ae.z *= inv; ae.w *= inv;
    ((float4*)g_aggc)[node * 32 + lane] = ac;
    ((float4*)g_agge)[node * 32 + lane] = ae;
}

// ---------------- layer 0: x3 = relu(aggc@Wl0 + x@Wr0 + b), x4 = relu(agge@Wl0 + x@Wr0 + b) ----------------
__global__ void layer0_kernel(const float* __restrict__ X,
                              const float* __restrict__ Wl, const float* __restrict__ Wr,
                              const float* __restrict__ bias,
                              float* __restrict__ O3, float* __restrict__ O4, int M) {
    __shared__ float sAc[64][24], sAe[64][24], sAx[64][24];
    __shared__ float sBl[16][64], sBr[16][64];
    int tid = threadIdx.x;
    int tx = tid & 15, ty = tid >> 4;
    int row0 = blockIdx.x * 64, col0 = blockIdx.y * 64;
    float accC[4][4], accE[4][4], accX[4][4];
    #pragma unroll
    for (int i = 0; i < 4; i++)
        #pragma unroll
        for (int j = 0; j < 4; j++) { accC[i][j] = 0.f; accE[i][j] = 0.f; accX[i][j] = 0.f; }

    int lm = tid >> 2;             // 0..63
    int lk4 = (tid & 3) << 2;      // 0,4,8,12
    int arow = row0 + lm; if (arow >= M) arow = M - 1;
    int kr = tid >> 4;             // 0..15
    int cq = (tid & 15) << 2;      // 0..60

    for (int k0 = 0; k0 < C; k0 += 16) {
        float4 v;
        v = *(const float4*)&g_aggc[arow * C + k0 + lk4]; *(float4*)&sAc[lm][lk4] = v;
        v = *(const float4*)&g_agge[arow * C + k0 + lk4]; *(float4*)&sAe[lm][lk4] = v;
        v = *(const float4*)&X[arow * C + k0 + lk4];      *(float4*)&sAx[lm][lk4] = v;
        v = *(const float4*)&Wl[(k0 + kr) * C + col0 + cq]; *(float4*)&sBl[kr][cq] = v;
        v = *(const float4*)&Wr[(k0 + kr) * C + col0 + cq]; *(float4*)&sBr[kr][cq] = v;
        __syncthreads();
        #pragma unroll
        for (int k = 0; k < 16; k++) {
            float bl[4], br[4];
            *(float4*)bl = *(float4*)&sBl[k][tx << 2];
            *(float4*)br = *(float4*)&sBr[k][tx << 2];
            #pragma unroll
            for (int i = 0; i < 4; i++) {
                float a_c = sAc[(ty << 2) + i][k];
                float a_e = sAe[(ty << 2) + i][k];
                float a_x = sAx[(ty << 2) + i][k];
                #pragma unroll
                for (int j = 0; j < 4; j++) {
                    accC[i][j] += a_c * bl[j];
                    accE[i][j] += a_e * bl[j];
                    accX[i][j] += a_x * br[j];
                }
            }
        }
        __syncthreads();
    }
    float4 b4 = *(const float4*)&bias[col0 + (tx << 2)];
    float bb[4] = {b4.x, b4.y, b4.z, b4.w};
    #pragma unroll
    for (int i = 0; i < 4; i++) {
        int r = row0 + (ty << 2) + i;
        if (r < M) {
            float4 o3, o4;
            float* p3 = (float*)&o3; float* p4 = (float*)&o4;
            #pragma unroll
            for (int j = 0; j < 4; j++) {
                p3[j] = fmaxf(accC[i][j] + accX[i][j] + bb[j], 0.f);
                p4[j] = fmaxf(accE[i][j] + accX[i][j] + bb[j], 0.f);
            }
            *(float4*)&O3[r * C + col0 + (tx << 2)] = o3;
            *(float4*)&O4[r * C + col0 + (tx << 2)] = o4;
        }
    }
}

// ---------------- layer 1: x1 = aggc2@Wl1 + x3@Wr1 + b ; x2 = agge2@Wl1 + x4@Wr1 + b ----------------
__global__ void layer1_kernel(const float* __restrict__ X3, const float* __restrict__ X4,
                              const float* __restrict__ Wl, const float* __restrict__ Wr,
                              const float* __restrict__ bias, int M) {
    __shared__ float sAc[64][24], sAe[64][24], sA3[64][24], sA4[64][24];
    __shared__ float sBl[16][64], sBr[16][64];
    int tid = threadIdx.x;
    int tx = tid & 15, ty = tid >> 4;
    int row0 = blockIdx.x * 64, col0 = blockIdx.y * 64;
    float acc1[4][4], acc2[4][4];
    #pragma unroll
    for (int i = 0; i < 4; i++)
        #pragma unroll
        for (int j = 0; j < 4; j++) { acc1[i][j] = 0.f; acc2[i][j] = 0.f; }

    int lm = tid >> 2;
    int lk4 = (tid & 3) << 2;
    int arow = row0 + lm; if (arow >= M) arow = M - 1;
    int kr = tid >> 4;
    int cq = (tid & 15) << 2;

    for (int k0 = 0; k0 < C; k0 += 16) {
        float4 v;
        v = *(const float4*)&g_aggc[arow * C + k0 + lk4]; *(float4*)&sAc[lm][lk4] = v;
        v = *(const float4*)&g_agge[arow * C + k0 + lk4]; *(float4*)&sAe[lm][lk4] = v;
        v = *(const float4*)&X3[arow * C + k0 + lk4];     *(float4*)&sA3[lm][lk4] = v;
        v = *(const float4*)&X4[arow * C + k0 + lk4];     *(float4*)&sA4[lm][lk4] = v;
        v = *(const float4*)&Wl[(k0 + kr) * C + col0 + cq]; *(float4*)&sBl[kr][cq] = v;
        v = *(const float4*)&Wr[(k0 + kr) * C + col0 + cq]; *(float4*)&sBr[kr][cq] = v;
        __syncthreads();
        #pragma unroll
        for (int k = 0; k < 16; k++) {
            float bl[4], br[4];
            *(float4*)bl = *(float4*)&sBl[k][tx << 2];
            *(float4*)br = *(float4*)&sBr[k][tx << 2];
            #pragma unroll
            for (int i = 0; i < 4; i++) {
                float a_c = sAc[(ty << 2) + i][k];
                float a_e = sAe[(ty << 2) + i][k];
                float a_3 = sA3[(ty << 2) + i][k];
                float a_4 = sA4[(ty << 2) + i][k];
                #pragma unroll
                for (int j = 0; j < 4; j++) {
                    acc1[i][j] += a_c * bl[j] + a_3 * br[j];
                    acc2[i][j] += a_e * bl[j] + a_4 * br[j];
                }
            }
        }
        __syncthreads();
    }
    float4 b4 = *(const float4*)&bias[col0 + (tx << 2)];
    float bb[4] = {b4.x, b4.y, b4.z, b4.w};
    #pragma unroll
    for (int i = 0; i < 4; i++) {
        int r = row0 + (ty << 2) + i;
        if (r < M) {
            float4 o1, o2;
            float* p1 = (float*)&o1; float* p2 = (float*)&o2;
            #pragma unroll
            for (int j = 0; j < 4; j++) {
                p1[j] = acc1[i][j] + bb[j];
                p2[j] = acc2[i][j] + bb[j];
            }
            *(float4*)&g_x1[r * C + col0 + (tx << 2)] = o1;
            *(float4*)&g_x2[r * C + col0 + (tx << 2)] = o2;
        }
    }
}

// ---------------- attention pooling: emb = sum_k softmax_k(tanh(z_k@W1+b1)@W2) * z_k ----------------
__global__ void attn_kernel(const float* __restrict__ X3, const float* __restrict__ X4,
                            const float* __restrict__ W1, const float* __restrict__ b1,
                            const float* __restrict__ W2,
                            float* __restrict__ emb, int N) {
    __shared__ float sW1[C * 64];  // [j][c] layout (as stored)
    __shared__ float sb1[64], sW2[64];
    int tid = threadIdx.x;
    for (int i = tid; i < C * 64; i += 256) sW1[i] = W1[i];
    if (tid < 64) { sb1[tid] = b1[tid]; sW2[tid] = W2[tid]; }
    __syncthreads();
    int warp = tid >> 5, lane = tid & 31;
    int nodebase = blockIdx.x * 64 + warp * 8;
    for (int n = 0; n < 8; n++) {
        int node = nodebase + n;
        if (node >= N) break;
        const float* zp[4];
        zp[0] = g_x1 + node * C;
        zp[1] = g_x2 + node * C;
        zp[2] = X3 + node * C;
        zp[3] = X4 + node * C;
        float s[4];
        #pragma unroll
        for (int k = 0; k < 4; k++) {
            float a0 = 0.f, a1 = 0.f;
            const float4* z4 = (const float4*)zp[k];
            #pragma unroll 8
            for (int jq = 0; jq < 32; jq++) {
                float4 z = __ldg(&z4[jq]);
                int j = jq << 2;
                a0 += z.x * sW1[(j + 0) * 64 + lane] + z.y * sW1[(j + 1) * 64 + lane]
                    + z.z * sW1[(j + 2) * 64 + lane] + z.w * sW1[(j + 3) * 64 + lane];
                a1 += z.x * sW1[(j + 0) * 64 + lane + 32] + z.y * sW1[(j + 1) * 64 + lane + 32]
                    + z.z * sW1[(j + 2) * 64 + lane + 32] + z.w * sW1[(j + 3) * 64 + lane + 32];
            }
            float t0 = tanhf(a0 + sb1[lane]);
            float t1 = tanhf(a1 + sb1[lane + 32]);
            float p = t0 * sW2[lane] + t1 * sW2[lane + 32];
            #pragma unroll
            for (int o = 16; o; o >>= 1) p += __shfl_xor_sync(0xffffffffu, p, o);
            s[k] = p;
        }
        float m = fmaxf(fmaxf(s[0], s[1]), fmaxf(s[2], s[3]));
        float e0 = expf(s[0] - m), e1 = expf(s[1] - m), e2 = expf(s[2] - m), e3 = expf(s[3] - m);
        float inv = 1.0f / (e0 + e1 + e2 + e3);
        float beta[4] = {e0 * inv, e1 * inv, e2 * inv, e3 * inv};
        float4 o = make_float4(0.f, 0.f, 0.f, 0.f);
        #pragma unroll
        for (int k = 0; k < 4; k++) {
            float4 z = __ldg(&((const float4*)zp[k])[lane]);
            o.x += beta[k] * z.x; o.y += beta[k] * z.y;
            o.z += beta[k] * z.z; o.w += beta[k] * z.w;
        }
        ((float4*)(emb + node * C))[lane] = o;
    }
}

// ---------------- launch ----------------
extern "C" void kernel_launch(void* const* d_in, const int* in_sizes, int n_in,
                              void* d_out, int out_size) {
    const float* x   = (const float*)d_in[0];
    const int*   row = (const int*)d_in[1];
    const int*   col = (const int*)d_in[2];
    const float* Wl0 = (const float*)d_in[3];
    const float* bl0 = (const float*)d_in[4];
    const float* Wr0 = (const float*)d_in[5];
    const float* Wl1 = (const float*)d_in[6];
    const float* bl1 = (const float*)d_in[7];
    const float* Wr1 = (const float*)d_in[8];
    const float* aW1 = (const float*)d_in[9];
    const float* ab1 = (const float*)d_in[10];
    const float* aW2 = (const float*)d_in[11];

    int N = in_sizes[0] / C;
    int E = in_sizes[1];

    float* emb = (float*)d_out;
    float* x3o = emb + (size_t)N * C;
    float* x4o = x3o + (size_t)N * C;

    int nb8 = (N + 7) / 8;
    int nbE = (E + 255) / 256;
    int nbM = (N + 63) / 64;

    zero_cnt_kernel<<<(N + 255) / 256, 256>>>(N);
    hist_kernel<<<nbE, 256>>>(row, E);
    scan_kernel<<<1, 1024>>>(N);
    fill_kernel<<<nbE, 256>>>(row, col, E);

    norm_kernel<<<nb8, 256>>>(x, N);
    edge1_kernel<<<nb8, 256>>>(x, N);
    layer0_kernel<<<dim3(nbM, 2), 256>>>(x, Wl0, Wr0, bl0, x3o, x4o, N);

    norm_kernel<<<nb8, 256>>>(x3o, N);
    edge2_kernel<<<nb8, 256>>>(x3o, x4o, N);
    layer1_kernel<<<dim3(nbM, 2), 256>>>(x3o, x4o, Wl1, Wr1, bl1, N);

    attn_kernel<<<nbM, 256>>>(x3o, x4o, aW1, ab1, aW2, emb, N);
}

// round 4
// speedup vs baseline: 1.2468x; 1.2468x over previous
#include <cuda_runtime.h>
#include <math.h>

typedef unsigned long long u64;

#define NMAX 50000
#define EMAX 800000
#define C 128

// ---------------- scratch (static __device__, no allocation) ----------------
__device__ int   g_cnt [NMAX];
__device__ int   g_fill[NMAX];
__device__ int   g_ptr [NMAX + 1];
__device__ int   g_ecol[EMAX];
__device__ float g_norm[NMAX];
__device__ float g_aggc[NMAX * C];
__device__ float g_agge[NMAX * C];
__device__ float g_x1  [NMAX * C];
__device__ float g_x2  [NMAX * C];
__device__ float g_scores[NMAX * 4];

// ---------------- packed fp32x2 helpers (SASS FFMA2) ----------------
__device__ __forceinline__ void ffma2(u64& d, u64 a, u64 b) {
    asm("fma.rn.f32x2 %0, %1, %2, %0;" : "+l"(d) : "l"(a), "l"(b));
}
__device__ __forceinline__ float lo32(u64 v) { return __uint_as_float((unsigned)v); }
__device__ __forceinline__ float hi32(u64 v) { return __uint_as_float((unsigned)(v >> 32)); }

// ---------------- CSR build ----------------
__global__ void zero_cnt_kernel(int N) {
    int i = blockIdx.x * blockDim.x + threadIdx.x;
    if (i < N) g_cnt[i] = 0;
}

__global__ void hist_kernel(const int* __restrict__ row, int E) {
    int i = blockIdx.x * blockDim.x + threadIdx.x;
    if (i < E) atomicAdd(&g_cnt[row[i]], 1);
}

__global__ void scan_kernel(int N) {
    __shared__ int sums[1024];
    int t = threadIdx.x;
    int chunk = (N + 1023) >> 10;
    int start = t * chunk;
    int end = min(start + chunk, N);
    int s = 0;
    for (int i = start; i < end; i++) s += g_cnt[i];
    sums[t] = s;
    __syncthreads();
    for (int off = 1; off < 1024; off <<= 1) {
        int v = (t >= off) ? sums[t - off] : 0;
        __syncthreads();
        sums[t] += v;
        __syncthreads();
    }
    int base = sums[t] - s;
    for (int i = start; i < end; i++) {
        g_ptr[i]  = base;
        g_fill[i] = base;
        base += g_cnt[i];
    }
    if (t == 0) g_ptr[N] = sums[1023];
}

__global__ void fill_kernel(const int* __restrict__ row, const int* __restrict__ col, int E) {
    int i = blockIdx.x * blockDim.x + threadIdx.x;
    if (i < E) {
        int r = row[i];
        int p = atomicAdd(&g_fill[r], 1);
        g_ecol[p] = col[i];
    }
}

// ---------------- per-node L2 norms ----------------
__global__ void norm_kernel(const float* __restrict__ X, int N) {
    int node = blockIdx.x * 8 + (threadIdx.x >> 5);
    int lane = threadIdx.x & 31;
    if (node >= N) return;
    float4 v = ((const float4*)X)[node * 32 + lane];
    float s = v.x * v.x + v.y * v.y + v.z * v.z + v.w * v.w;
    #pragma unroll
    for (int o = 16; o; o >>= 1) s += __shfl_xor_sync(0xffffffffu, s, o);
    if (lane == 0) g_norm[node] = sqrtf(s);
}

// ---------------- edge pass 1: cos + eud on x, fused gather-aggregate ----------------
__global__ void edge1_kernel(const float* __restrict__ X, int N) {
    int node = blockIdx.x * 8 + (threadIdx.x >> 5);
    int lane = threadIdx.x & 31;
    if (node >= N) return;
    const float4* X4 = (const float4*)X;
    float4 xi = X4[node * 32 + lane];
    float ni = g_norm[node];
    int s = g_ptr[node], e = g_ptr[node + 1];
    float4 ac = make_float4(0.f, 0.f, 0.f, 0.f);
    float4 ae = make_float4(0.f, 0.f, 0.f, 0.f);
    for (int j = s; j < e; j++) {
        int c = g_ecol[j];
        float4 xc = __ldg(&X4[c * 32 + lane]);
        float nc = __ldg(&g_norm[c]);
        float d = xi.x * xc.x + xi.y * xc.y + xi.z * xc.z + xi.w * xc.w;
        float ux = xi.x - xc.x + 1e-6f;
        float uy = xi.y - xc.y + 1e-6f;
        float uz = xi.z - xc.z + 1e-6f;
        float uw = xi.w - xc.w + 1e-6f;
        float u = ux * ux + uy * uy + uz * uz + uw * uw;
        #pragma unroll
        for (int o = 16; o; o >>= 1) {
            d += __shfl_xor_sync(0xffffffffu, d, o);
            u += __shfl_xor_sync(0xffffffffu, u, o);
        }
        float ecos = d / fmaxf(ni * nc, 1e-8f);
        float eeud = sqrtf(u);
        ac.x += ecos * xc.x; ac.y += ecos * xc.y; ac.z += ecos * xc.z; ac.w += ecos * xc.w;
        ae.x += eeud * xc.x; ae.y += eeud * xc.y; ae.z += eeud * xc.z; ae.w += eeud * xc.w;
    }
    float inv = 1.0f / fmaxf((float)(e - s), 1.0f);
    ac.x *= inv; ac.y *= inv; ac.z *= inv; ac.w *= inv;
    ae.x *= inv; ae.y *= inv; ae.z *= inv; ae.w *= inv;
    ((float4*)g_aggc)[node * 32 + lane] = ac;
    ((float4*)g_agge)[node * 32 + lane] = ae;
}

// ---------------- edge pass 2: cos on x3, eud on x4 ----------------
__global__ void edge2_kernel(const float* __restrict__ X3, const float* __restrict__ X4, int N) {
    int node = blockIdx.x * 8 + (threadIdx.x >> 5);
    int lane = threadIdx.x & 31;
    if (node >= N) return;
    const float4* A4 = (const float4*)X3;
    const float4* B4 = (const float4*)X4;
    float4 x3i = A4[node * 32 + lane];
    float4 x4i = B4[node * 32 + lane];
    float n3 = g_norm[node];
    int s = g_ptr[node], e = g_ptr[node + 1];
    float4 ac = make_float4(0.f, 0.f, 0.f, 0.f);
    float4 ae = make_float4(0.f, 0.f, 0.f, 0.f);
    for (int j = s; j < e; j++) {
        int c = g_ecol[j];
        float4 xc3 = __ldg(&A4[c * 32 + lane]);
        float4 xc4 = __ldg(&B4[c * 32 + lane]);
        float nc = __ldg(&g_norm[c]);
        float d = x3i.x * xc3.x + x3i.y * xc3.y + x3i.z * xc3.z + x3i.w * xc3.w;
        float ux = x4i.x - xc4.x + 1e-6f;
        float uy = x4i.y - xc4.y + 1e-6f;
        float uz = x4i.z - xc4.z + 1e-6f;
        float uw = x4i.w - xc4.w + 1e-6f;
        float u = ux * ux + uy * uy + uz * uz + uw * uw;
        #pragma unroll
        for (int o = 16; o; o >>= 1) {
            d += __shfl_xor_sync(0xffffffffu, d, o);
            u += __shfl_xor_sync(0xffffffffu, u, o);
        }
        float ecos = d / fmaxf(n3 * nc, 1e-8f);
        float eeud = sqrtf(u);
        ac.x += ecos * xc3.x; ac.y += ecos * xc3.y; ac.z += ecos * xc3.z; ac.w += ecos * xc3.w;
        ae.x += eeud * xc4.x; ae.y += eeud * xc4.y; ae.z += eeud * xc4.z; ae.w += eeud * xc4.w;
    }
    float inv = 1.0f / fmaxf((float)(e - s), 1.0f);
    ac.x *= inv; ac.y *= inv; ac.z *= inv; ac.w *= inv;
    ae.x *= inv; ae.y *= inv; ae.z *= inv; ae.w *= inv;
    ((float4*)g_aggc)[node * 32 + lane] = ac;
    ((float4*)g_agge)[node * 32 + lane] = ae;
}

// ---------------- layer 0 (f32x2): x3 = relu(aggc@Wl + x@Wr + b), x4 = relu(agge@Wl + x@Wr + b) ----------------
__global__ void layer0_kernel(const float* __restrict__ X,
                              const float* __restrict__ Wl, const float* __restrict__ Wr,
                              const float* __restrict__ bias,
                              float* __restrict__ O3, float* __restrict__ O4, int M) {
    __shared__ __align__(16) float sAc[64][36], sAe[64][36], sAx[64][36];  // A duplicated {a,a}
    __shared__ __align__(16) float sBl[16][68], sBr[16][68];
    int tid = threadIdx.x;
    int tx = tid & 15, ty = tid >> 4;
    int row0 = blockIdx.x * 64, col0 = blockIdx.y * 64;
    u64 accC[4][2], accE[4][2], accX[4][2];
    #pragma unroll
    for (int i = 0; i < 4; i++) {
        accC[i][0] = accC[i][1] = 0ull;
        accE[i][0] = accE[i][1] = 0ull;
        accX[i][0] = accX[i][1] = 0ull;
    }
    int lm = tid >> 2, lk4 = (tid & 3) << 2;
    int arow = row0 + lm; if (arow >= M) arow = M - 1;
    int cq = tx << 2;

    for (int k0 = 0; k0 < C; k0 += 16) {
        float4 v;
        v = *(const float4*)&g_aggc[arow * C + k0 + lk4];
        *(float4*)&sAc[lm][2 * lk4]     = make_float4(v.x, v.x, v.y, v.y);
        *(float4*)&sAc[lm][2 * lk4 + 4] = make_float4(v.z, v.z, v.w, v.w);
        v = *(const float4*)&g_agge[arow * C + k0 + lk4];
        *(float4*)&sAe[lm][2 * lk4]     = make_float4(v.x, v.x, v.y, v.y);
        *(float4*)&sAe[lm][2 * lk4 + 4] = make_float4(v.z, v.z, v.w, v.w);
        v = *(const float4*)&X[arow * C + k0 + lk4];
        *(float4*)&sAx[lm][2 * lk4]     = make_float4(v.x, v.x, v.y, v.y);
        *(float4*)&sAx[lm][2 * lk4 + 4] = make_float4(v.z, v.z, v.w, v.w);
        *(float4*)&sBl[ty][cq] = *(const float4*)&Wl[(k0 + ty) * C + col0 + cq];
        *(float4*)&sBr[ty][cq] = *(const float4*)&Wr[(k0 + ty) * C + col0 + cq];
        __syncthreads();
        #pragma unroll
        for (int k = 0; k < 16; k++) {
            ulonglong2 bl = *(const ulonglong2*)&sBl[k][cq];
            ulonglong2 br = *(const ulonglong2*)&sBr[k][cq];
            #pragma unroll
            for (int i = 0; i < 4; i++) {
                u64 a_c = *(const u64*)&sAc[(ty << 2) + i][2 * k];
                u64 a_e = *(const u64*)&sAe[(ty << 2) + i][2 * k];
                u64 a_x = *(const u64*)&sAx[(ty << 2) + i][2 * k];
                ffma2(accC[i][0], a_c, bl.x); ffma2(accC[i][1], a_c, bl.y);
                ffma2(accE[i][0], a_e, bl.x); ffma2(accE[i][1], a_e, bl.y);
                ffma2(accX[i][0], a_x, br.x); ffma2(accX[i][1], a_x, br.y);
            }
        }
        __syncthreads();
    }
    float4 b4 = *(const float4*)&bias[col0 + cq];
    float bb[4] = {b4.x, b4.y, b4.z, b4.w};
    #pragma unroll
    for (int i = 0; i < 4; i++) {
        int r = row0 + (ty << 2) + i;
        if (r < M) {
            float c[4] = {lo32(accC[i][0]), hi32(accC[i][0]), lo32(accC[i][1]), hi32(accC[i][1])};
            float e[4] = {lo32(accE[i][0]), hi32(accE[i][0]), lo32(accE[i][1]), hi32(accE[i][1])};
            float x[4] = {lo32(accX[i][0]), hi32(accX[i][0]), lo32(accX[i][1]), hi32(accX[i][1])};
            float4 o3, o4;
            float* p3 = (float*)&o3; float* p4 = (float*)&o4;
            #pragma unroll
            for (int j = 0; j < 4; j++) {
                p3[j] = fmaxf(c[j] + x[j] + bb[j], 0.f);
                p4[j] = fmaxf(e[j] + x[j] + bb[j], 0.f);
            }
            *(float4*)&O3[r * C + col0 + cq] = o3;
            *(float4*)&O4[r * C + col0 + cq] = o4;
        }
    }
}

// ---------------- layer 1 (f32x2): x1 = aggc@Wl + x3@Wr + b ; x2 = agge@Wl + x4@Wr + b ----------------
__global__ void layer1_kernel(const float* __restrict__ X3, const float* __restrict__ X4,
                              const float* __restrict__ Wl, const float* __restrict__ Wr,
                              const float* __restrict__ bias, int M) {
    __shared__ __align__(16) float sAc[64][36], sAe[64][36], sA3[64][36], sA4[64][36];
    __shared__ __align__(16) float sBl[16][68], sBr[16][68];
    int tid = threadIdx.x;
    int tx = tid & 15, ty = tid >> 4;
    int row0 = blockIdx.x * 64, col0 = blockIdx.y * 64;
    u64 acc1[4][2], acc2[4][2];
    #pragma unroll
    for (int i = 0; i < 4; i++) {
        acc1[i][0] = acc1[i][1] = 0ull;
        acc2[i][0] = acc2[i][1] = 0ull;
    }
    int lm = tid >> 2, lk4 = (tid & 3) << 2;
    int arow = row0 + lm; if (arow >= M) arow = M - 1;
    int cq = tx << 2;

    for (int k0 = 0; k0 < C; k0 += 16) {
        float4 v;
        v = *(const float4*)&g_aggc[arow * C + k0 + lk4];
        *(float4*)&sAc[lm][2 * lk4]     = make_float4(v.x, v.x, v.y, v.y);
        *(float4*)&sAc[lm][2 * lk4 + 4] = make_float4(v.z, v.z, v.w, v.w);
        v = *(const float4*)&g_agge[arow * C + k0 + lk4];
        *(float4*)&sAe[lm][2 * lk4]     = make_float4(v.x, v.x, v.y, v.y);
        *(float4*)&sAe[lm][2 * lk4 + 4] = make_float4(v.z, v.z, v.w, v.w);
        v = *(const float4*)&X3[arow * C + k0 + lk4];
        *(float4*)&sA3[lm][2 * lk4]     = make_float4(v.x, v.x, v.y, v.y);
        *(float4*)&sA3[lm][2 * lk4 + 4] = make_float4(v.z, v.z, v.w, v.w);
        v = *(const float4*)&X4[arow * C + k0 + lk4];
        *(float4*)&sA4[lm][2 * lk4]     = make_float4(v.x, v.x, v.y, v.y);
        *(float4*)&sA4[lm][2 * lk4 + 4] = make_float4(v.z, v.z, v.w, v.w);
        *(float4*)&sBl[ty][cq] = *(const float4*)&Wl[(k0 + ty) * C + col0 + cq];
        *(float4*)&sBr[ty][cq] = *(const float4*)&Wr[(k0 + ty) * C + col0 + cq];
        __syncthreads();
        #pragma unroll
        for (int k = 0; k < 16; k++) {
            ulonglong2 bl = *(const ulonglong2*)&sBl[k][cq];
            ulonglong2 br = *(const ulonglong2*)&sBr[k][cq];
            #pragma unroll
            for (int i = 0; i < 4; i++) {
                u64 a_c = *(const u64*)&sAc[(ty << 2) + i][2 * k];
                u64 a_e = *(const u64*)&sAe[(ty << 2) + i][2 * k];
                u64 a_3 = *(const u64*)&sA3[(ty << 2) + i][2 * k];
                u64 a_4 = *(const u64*)&sA4[(ty << 2) + i][2 * k];
                ffma2(acc1[i][0], a_c, bl.x); ffma2(acc1[i][1], a_c, bl.y);
                ffma2(acc1[i][0], a_3, br.x); ffma2(acc1[i][1], a_3, br.y);
                ffma2(acc2[i][0], a_e, bl.x); ffma2(acc2[i][1], a_e, bl.y);
                ffma2(acc2[i][0], a_4, br.x); ffma2(acc2[i][1], a_4, br.y);
            }
        }
        __syncthreads();
    }
    float4 b4 = *(const float4*)&bias[col0 + cq];
    float bb[4] = {b4.x, b4.y, b4.z, b4.w};
    #pragma unroll
    for (int i = 0; i < 4; i++) {
        int r = row0 + (ty << 2) + i;
        if (r < M) {
            float a[4] = {lo32(acc1[i][0]), hi32(acc1[i][0]), lo32(acc1[i][1]), hi32(acc1[i][1])};
            float b[4] = {lo32(acc2[i][0]), hi32(acc2[i][0]), lo32(acc2[i][1]), hi32(acc2[i][1])};
            float4 o1, o2;
            float* p1 = (float*)&o1; float* p2 = (float*)&o2;
            #pragma unroll
            for (int j = 0; j < 4; j++) {
                p1[j] = a[j] + bb[j];
                p2[j] = b[j] + bb[j];
            }
            *(float4*)&g_x1[r * C + col0 + cq] = o1;
            *(float4*)&g_x2[r * C + col0 + cq] = o2;
        }
    }
}

// ---------------- attention scores as GEMM: s[r] = tanh(z_r@W1 + b1)@W2, r = node*4+branch ----------------
__global__ void score_kernel(const float* __restrict__ X3, const float* __restrict__ X4,
                             const float* __restrict__ W1, const float* __restrict__ b1,
                             const float* __restrict__ W2, int R) {
    __shared__ __align__(16) float sA[64][36];
    __shared__ __align__(16) float sB[16][68];
    int tid = threadIdx.x;
    int tx = tid & 15, ty = tid >> 4;
    int row0 = blockIdx.x * 64;
    u64 acc[4][2];
    #pragma unroll
    for (int i = 0; i < 4; i++) { acc[i][0] = acc[i][1] = 0ull; }
    int lm = tid >> 2, lk4 = (tid & 3) << 2;
    int r = row0 + lm; if (r >= R) r = R - 1;
    int branch = r & 3, node = r >> 2;
    const float* zrow;
    if (branch == 0)      zrow = g_x1 + (size_t)node * C;
    else if (branch == 1) zrow = g_x2 + (size_t)node * C;
    else if (branch == 2) zrow = X3 + (size_t)node * C;
    else                  zrow = X4 + (size_t)node * C;
    int cq = tx << 2;

    for (int k0 = 0; k0 < C; k0 += 16) {
        float4 v = *(const float4*)&zrow[k0 + lk4];
        *(float4*)&sA[lm][2 * lk4]     = make_float4(v.x, v.x, v.y, v.y);
        *(float4*)&sA[lm][2 * lk4 + 4] = make_float4(v.z, v.z, v.w, v.w);
        *(float4*)&sB[ty][cq] = *(const float4*)&W1[(k0 + ty) * 64 + cq];
        __syncthreads();
        #pragma unroll
        for (int k = 0; k < 16; k++) {
            ulonglong2 b = *(const ulonglong2*)&sB[k][cq];
            #pragma unroll
            for (int i = 0; i < 4; i++) {
                u64 a = *(const u64*)&sA[(ty << 2) + i][2 * k];
                ffma2(acc[i][0], a, b.x);
                ffma2(acc[i][1], a, b.y);
            }
        }
        __syncthreads();
    }
    float4 bb = *(const float4*)&b1[cq];
    float4 w2 = *(const float4*)&W2[cq];
    #pragma unroll
    for (int i = 0; i < 4; i++) {
        float t0 = tanhf(lo32(acc[i][0]) + bb.x);
        float t1 = tanhf(hi32(acc[i][0]) + bb.y);
        float t2 = tanhf(lo32(acc[i][1]) + bb.z);
        float t3 = tanhf(hi32(acc[i][1]) + bb.w);
        float s = t0 * w2.x + t1 * w2.y + t2 * w2.z + t3 * w2.w;
        #pragma unroll
        for (int o = 8; o; o >>= 1) s += __shfl_xor_sync(0xffffffffu, s, o);
        if (tx == 0) {
            int rr = row0 + (ty << 2) + i;
            if (rr < R) g_scores[rr] = s;
        }
    }
}

// ---------------- softmax + weighted pooling ----------------
__global__ void pool_kernel(const float* __restrict__ X3, const float* __restrict__ X4,
                            float* __restrict__ emb, int N) {
    int node = blockIdx.x * 8 + (threadIdx.x >> 5);
    int lane = threadIdx.x & 31;
    if (node >= N) return;
    float s0 = g_scores[node * 4 + 0];
    float s1 = g_scores[node * 4 + 1];
    float s2 = g_scores[node * 4 + 2];
    float s3 = g_scores[node * 4 + 3];
    float m = fmaxf(fmaxf(s0, s1), fmaxf(s2, s3));
    float e0 = expf(s0 - m), e1 = expf(s1 - m), e2 = expf(s2 - m), e3 = expf(s3 - m);
    float inv = 1.0f / (e0 + e1 + e2 + e3);
    float b0 = e0 * inv, b1 = e1 * inv, b2 = e2 * inv, b3 = e3 * inv;
    float4 z1 = __ldg(&((const float4*)(g_x1 + (size_t)node * C))[lane]);
    float4 z2 = __ldg(&((const float4*)(g_x2 + (size_t)node * C))[lane]);
    float4 z3 = __ldg(&((const float4*)(X3 + (size_t)node * C))[lane]);
    float4 z4 = __ldg(&((const float4*)(X4 + (size_t)node * C))[lane]);
    float4 o;
    o.x = b0 * z1.x + b1 * z2.x + b2 * z3.x + b3 * z4.x;
    o.y = b0 * z1.y + b1 * z2.y + b2 * z3.y + b3 * z4.y;
    o.z = b0 * z1.z + b1 * z2.z + b2 * z3.z + b3 * z4.z;
    o.w = b0 * z1.w + b1 * z2.w + b2 * z3.w + b3 * z4.w;
    ((float4*)(emb + (size_t)node * C))[lane] = o;
}

// ---------------- launch ----------------
extern "C" void kernel_launch(void* const* d_in, const int* in_sizes, int n_in,
                              void* d_out, int out_size) {
    const float* x   = (const float*)d_in[0];
    const int*   row = (const int*)d_in[1];
    const int*   col = (const int*)d_in[2];
    const float* Wl0 = (const float*)d_in[3];
    const float* bl0 = (const float*)d_in[4];
    const float* Wr0 = (const float*)d_in[5];
    const float* Wl1 = (const float*)d_in[6];
    const float* bl1 = (const float*)d_in[7];
    const float* Wr1 = (const float*)d_in[8];
    const float* aW1 = (const float*)d_in[9];
    const float* ab1 = (const float*)d_in[10];
    const float* aW2 = (const float*)d_in[11];

    int N = in_sizes[0] / C;
    int E = in_sizes[1];

    float* emb = (float*)d_out;
    float* x3o = emb + (size_t)N * C;
    float* x4o = x3o + (size_t)N * C;

    int nb8 = (N + 7) / 8;
    int nbE = (E + 255) / 256;
    int nbM = (N + 63) / 64;
    int nbS = (4 * N + 63) / 64;

    zero_cnt_kernel<<<(N + 255) / 256, 256>>>(N);
    hist_kernel<<<nbE, 256>>>(row, E);
    scan_kernel<<<1, 1024>>>(N);
    fill_kernel<<<nbE, 256>>>(row, col, E);

    norm_kernel<<<nb8, 256>>>(x, N);
    edge1_kernel<<<nb8, 256>>>(x, N);
    layer0_kernel<<<dim3(nbM, 2), 256>>>(x, Wl0, Wr0, bl0, x3o, x4o, N);

    norm_kernel<<<nb8, 256>>>(x3o, N);
    edge2_kernel<<<nb8, 256>>>(x3o, x4o, N);
    layer1_kernel<<<dim3(nbM, 2), 256>>>(x3o, x4o, Wl1, Wr1, bl1, N);

    score_kernel<<<nbS, 256>>>(x3o, x4o, aW1, ab1, aW2, 4 * N);
    pool_kernel<<<nb8, 256>>>(x3o, x4o, emb, N);
}

// round 7
// speedup vs baseline: 1.4045x; 1.1265x over previous
#include <cuda_runtime.h>
#include <math.h>

typedef unsigned long long u64;

#define NMAX 50000
#define EMAX 800000
#define C 128

// ---------------- scratch (static __device__, no allocation) ----------------
__device__ int   g_cnt [NMAX];
__device__ int   g_fill[NMAX];
__device__ int   g_ptr [NMAX + 1];
__device__ int   g_ecol[EMAX];
__device__ float g_norm[NMAX];
__device__ float g_aggc[NMAX * C];
__device__ float g_agge[NMAX * C];
__device__ float g_x1  [NMAX * C];
__device__ float g_x2  [NMAX * C];
__device__ float g_scores[NMAX * 4];

// ---------------- packed fp32x2 helpers (SASS FFMA2) ----------------
__device__ __forceinline__ void ffma2(u64& d, u64 a, u64 b) {
    asm("fma.rn.f32x2 %0, %1, %2, %0;" : "+l"(d) : "l"(a), "l"(b));
}
__device__ __forceinline__ float lo32(u64 v) { return __uint_as_float((unsigned)v); }
__device__ __forceinline__ float hi32(u64 v) { return __uint_as_float((unsigned)(v >> 32)); }

// ---------------- CSR build ----------------
__global__ void zero_cnt_kernel(int N) {
    int i = blockIdx.x * blockDim.x + threadIdx.x;
    if (i < N) g_cnt[i] = 0;
}

__global__ void hist_kernel(const int* __restrict__ row, int E) {
    int i = blockIdx.x * blockDim.x + threadIdx.x;
    if (i < E) atomicAdd(&g_cnt[row[i]], 1);
}

__global__ void scan_kernel(int N) {
    __shared__ int sums[1024];
    int t = threadIdx.x;
    int chunk = (N + 1023) >> 10;
    int start = t * chunk;
    int end = min(start + chunk, N);
    int s = 0;
    for (int i = start; i < end; i++) s += g_cnt[i];
    sums[t] = s;
    __syncthreads();
    for (int off = 1; off < 1024; off <<= 1) {
        int v = (t >= off) ? sums[t - off] : 0;
        __syncthreads();
        sums[t] += v;
        __syncthreads();
    }
    int base = sums[t] - s;
    for (int i = start; i < end; i++) {
        g_ptr[i]  = base;
        g_fill[i] = base;
        base += g_cnt[i];
    }
    if (t == 0) g_ptr[N] = sums[1023];
}

__global__ void fill_kernel(const int* __restrict__ row, const int* __restrict__ col, int E) {
    int i = blockIdx.x * blockDim.x + threadIdx.x;
    if (i < E) {
        int r = row[i];
        int p = atomicAdd(&g_fill[r], 1);
        g_ecol[p] = col[i];
    }
}

// ---------------- per-node L2 norms ----------------
__global__ void norm_kernel(const float* __restrict__ X, int N) {
    int node = blockIdx.x * 8 + (threadIdx.x >> 5);
    int lane = threadIdx.x & 31;
    if (node >= N) return;
    float4 v = ((const float4*)X)[node * 32 + lane];
    float s = v.x * v.x + v.y * v.y + v.z * v.z + v.w * v.w;
    #pragma unroll
    for (int o = 16; o; o >>= 1) s += __shfl_xor_sync(0xffffffffu, s, o);
    if (lane == 0) g_norm[node] = sqrtf(s);
}

// ---------------- edge pass 1: cos + eud on x, fused gather-aggregate ----------------
__global__ void edge1_kernel(const float* __restrict__ X, int N) {
    int node = blockIdx.x * 8 + (threadIdx.x >> 5);
    int lane = threadIdx.x & 31;
    if (node >= N) return;
    const float4* X4 = (const float4*)X;
    float4 xi = X4[node * 32 + lane];
    float ni = g_norm[node];
    int s = g_ptr[node], e = g_ptr[node + 1];
    float4 ac = make_float4(0.f, 0.f, 0.f, 0.f);
    float4 ae = make_float4(0.f, 0.f, 0.f, 0.f);
    int cNext = (s < e) ? __ldg(&g_ecol[s]) : 0;
    for (int j = s; j < e; j++) {
        int c = cNext;
        if (j + 1 < e) cNext = __ldg(&g_ecol[j + 1]);
        float4 xc = __ldg(&X4[c * 32 + lane]);
        float nc = __ldg(&g_norm[c]);
        float d = xi.x * xc.x + xi.y * xc.y + xi.z * xc.z + xi.w * xc.w;
        float ux = xi.x - xc.x + 1e-6f;
        float uy = xi.y - xc.y + 1e-6f;
        float uz = xi.z - xc.z + 1e-6f;
        float uw = xi.w - xc.w + 1e-6f;
        float u = ux * ux + uy * uy + uz * uz + uw * uw;
        #pragma unroll
        for (int o = 16; o; o >>= 1) {
            d += __shfl_xor_sync(0xffffffffu, d, o);
            u += __shfl_xor_sync(0xffffffffu, u, o);
        }
        float ecos = d / fmaxf(ni * nc, 1e-8f);
        float eeud = sqrtf(u);
        ac.x += ecos * xc.x; ac.y += ecos * xc.y; ac.z += ecos * xc.z; ac.w += ecos * xc.w;
        ae.x += eeud * xc.x; ae.y += eeud * xc.y; ae.z += eeud * xc.z; ae.w += eeud * xc.w;
    }
    float inv = 1.0f / fmaxf((float)(e - s), 1.0f);
    ac.x *= inv; ac.y *= inv; ac.z *= inv; ac.w *= inv;
    ae.x *= inv; ae.y *= inv; ae.z *= inv; ae.w *= inv;
    ((float4*)g_aggc)[node * 32 + lane] = ac;
    ((float4*)g_agge)[node * 32 + lane] = ae;
}

// ---------------- edge pass 2: cos on x3, eud on x4 ----------------
__global__ void edge2_kernel(const float* __restrict__ X3, const float* __restrict__ X4, int N) {
    int node = blockIdx.x * 8 + (threadIdx.x >> 5);
    int lane = threadIdx.x & 31;
    if (node >= N) return;
    const float4* A4 = (const float4*)X3;
    const float4* B4 = (const float4*)X4;
    float4 x3i = A4[node * 32 + lane];
    float4 x4i = B4[node * 32 + lane];
    float n3 = g_norm[node];
    int s = g_ptr[node], e = g_ptr[node + 1];
    float4 ac = make_float4(0.f, 0.f, 0.f, 0.f);
    float4 ae = make_float4(0.f, 0.f, 0.f, 0.f);
    int cNext = (s < e) ? __ldg(&g_ecol[s]) : 0;
    for (int j = s; j < e; j++) {
        int c = cNext;
        if (j + 1 < e) cNext = __ldg(&g_ecol[j + 1]);
        float4 xc3 = __ldg(&A4[c * 32 + lane]);
        float4 xc4 = __ldg(&B4[c * 32 + lane]);
        float nc = __ldg(&g_norm[c]);
        float d = x3i.x * xc3.x + x3i.y * xc3.y + x3i.z * xc3.z + x3i.w * xc3.w;
        float ux = x4i.x - xc4.x + 1e-6f;
        float uy = x4i.y - xc4.y + 1e-6f;
        float uz = x4i.z - xc4.z + 1e-6f;
        float uw = x4i.w - xc4.w + 1e-6f;
        float u = ux * ux + uy * uy + uz * uz + uw * uw;
        #pragma unroll
        for (int o = 16; o; o >>= 1) {
            d += __shfl_xor_sync(0xffffffffu, d, o);
            u += __shfl_xor_sync(0xffffffffu, u, o);
        }
        float ecos = d / fmaxf(n3 * nc, 1e-8f);
        float eeud = sqrtf(u);
        ac.x += ecos * xc3.x; ac.y += ecos * xc3.y; ac.z += ecos * xc3.z; ac.w += ecos * xc3.w;
        ae.x += eeud * xc4.x; ae.y += eeud * xc4.y; ae.z += eeud * xc4.z; ae.w += eeud * xc4.w;
    }
    float inv = 1.0f / fmaxf((float)(e - s), 1.0f);
    ac.x *= inv; ac.y *= inv; ac.z *= inv; ac.w *= inv;
    ae.x *= inv; ae.y *= inv; ae.z *= inv; ae.w *= inv;
    ((float4*)g_aggc)[node * 32 + lane] = ac;
    ((float4*)g_agge)[node * 32 + lane] = ae;
}

// ==================== GEMM kernels: 64/128 rows x 128/64 cols, strided col pairs ====================
// Thread (tx,ty): owns rows ty*4..+3, col pairs {2tx+32j} (layer) / {2tx+16j} (score).
// B smem reads: LDS64 at u64-index tx+16j -> bank 2tx, conflict-free broadcast.
// A smem: duplicated {a,a} pairs, row stride 36 floats, broadcast reads.

// ---------------- layer 0: x3 = relu(aggc@Wl + x@Wr + b), x4 = relu(agge@Wl + x@Wr + b) ----------------
__global__ void layer0_kernel(const float* __restrict__ X,
                              const float* __restrict__ Wl, const float* __restrict__ Wr,
                              const float* __restrict__ bias,
                              float* __restrict__ O3, float* __restrict__ O4, int M) {
    __shared__ __align__(16) float sAc[64][36], sAe[64][36], sAx[64][36];
    __shared__ __align__(16) float sBl[16][128], sBr[16][128];
    int tid = threadIdx.x;
    int tx = tid & 15, ty = tid >> 4;        // tx: 16 col-pair groups, ty: 16 row groups
    int row0 = blockIdx.x * 64;
    u64 accC[4][4], accE[4][4], accX[4][4];
    #pragma unroll
    for (int i = 0; i < 4; i++)
        #pragma unroll
        for (int j = 0; j < 4; j++) { accC[i][j] = 0; accE[i][j] = 0; accX[i][j] = 0; }

    int lm = tid >> 2, q = tid & 3;          // A loader: row lm, quarter q
    int arow = row0 + lm; if (arow >= M) arow = M - 1;
    int kr = tid >> 4, cb = (tid & 15) * 8;  // B loader

    for (int k0 = 0; k0 < C; k0 += 16) {
        float4 v;
        v = *(const float4*)&g_aggc[arow * C + k0 + q * 4];
        *(float4*)&sAc[lm][8 * q]     = make_float4(v.x, v.x, v.y, v.y);
        *(float4*)&sAc[lm][8 * q + 4] = make_float4(v.z, v.z, v.w, v.w);
        v = *(const float4*)&g_agge[arow * C + k0 + q * 4];
        *(float4*)&sAe[lm][8 * q]     = make_float4(v.x, v.x, v.y, v.y);
        *(float4*)&sAe[lm][8 * q + 4] = make_float4(v.z, v.z, v.w, v.w);
        v = *(const float4*)&X[arow * C + k0 + q * 4];
        *(float4*)&sAx[lm][8 * q]     = make_float4(v.x, v.x, v.y, v.y);
        *(float4*)&sAx[lm][8 * q + 4] = make_float4(v.z, v.z, v.w, v.w);
        *(float4*)&sBl[kr][cb]     = *(const float4*)&Wl[(k0 + kr) * C + cb];
        *(float4*)&sBl[kr][cb + 4] = *(const float4*)&Wl[(k0 + kr) * C + cb + 4];
        *(float4*)&sBr[kr][cb]     = *(const float4*)&Wr[(k0 + kr) * C + cb];
        *(float4*)&sBr[kr][cb + 4] = *(const float4*)&Wr[(k0 + kr) * C + cb + 4];
        __syncthreads();
        #pragma unroll
        for (int k = 0; k < 16; k++) {
            const u64* pl = (const u64*)&sBl[k][0];
            const u64* pr = (const u64*)&sBr[k][0];
            u64 bl[4], br[4];
            #pragma unroll
            for (int j = 0; j < 4; j++) { bl[j] = pl[tx + 16 * j]; br[j] = pr[tx + 16 * j]; }
            #pragma unroll
            for (int i = 0; i < 4; i++) {
                u64 a_c = *(const u64*)&sAc[(ty << 2) + i][2 * k];
                u64 a_e = *(const u64*)&sAe[(ty << 2) + i][2 * k];
                u64 a_x = *(const u64*)&sAx[(ty << 2) + i][2 * k];
                #pragma unroll
                for (int j = 0; j < 4; j++) {
                    ffma2(accC[i][j], a_c, bl[j]);
                    ffma2(accE[i][j], a_e, bl[j]);
                    ffma2(accX[i][j], a_x, br[j]);
                }
            }
        }
        __syncthreads();
    }
    #pragma unroll
    for (int i = 0; i < 4; i++) {
        int r = row0 + (ty << 2) + i;
        if (r < M) {
            #pragma unroll
            for (int j = 0; j < 4; j++) {
                int c0 = 2 * tx + 32 * j;
                float2 bb = *(const float2*)&bias[c0];
                float2 o3, o4;
                float xlo = lo32(accX[i][j]), xhi = hi32(accX[i][j]);
                o3.x = fmaxf(lo32(accC[i][j]) + xlo + bb.x, 0.f);
                o3.y = fmaxf(hi32(accC[i][j]) + xhi + bb.y, 0.f);
                o4.x = fmaxf(lo32(accE[i][j]) + xlo + bb.x, 0.f);
                o4.y = fmaxf(hi32(accE[i][j]) + xhi + bb.y, 0.f);
                *(float2*)&O3[r * C + c0] = o3;
                *(float2*)&O4[r * C + c0] = o4;
            }
        }
    }
}

// ---------------- layer 1: x1 = aggc@Wl + x3@Wr + b ; x2 = agge@Wl + x4@Wr + b ----------------
__global__ void layer1_kernel(const float* __restrict__ X3, const float* __restrict__ X4,
                              const float* __restrict__ Wl, const float* __restrict__ Wr,
                              const float* __restrict__ bias, int M) {
    __shared__ __align__(16) float sAc[64][36], sAe[64][36], sA3[64][36], sA4[64][36];
    __shared__ __align__(16) float sBl[16][128], sBr[16][128];
    int tid = threadIdx.x;
    int tx = tid & 15, ty = tid >> 4;
    int row0 = blockIdx.x * 64;
    u64 acc1[4][4], acc2[4][4];
    #pragma unroll
    for (int i = 0; i < 4; i++)
        #pragma unroll
        for (int j = 0; j < 4; j++) { acc1[i][j] = 0; acc2[i][j] = 0; }

    int lm = tid >> 2, q = tid & 3;
    int arow = row0 + lm; if (arow >= M) arow = M - 1;
    int kr = tid >> 4, cb = (tid & 15) * 8;

    for (int k0 = 0; k0 < C; k0 += 16) {
        float4 v;
        v = *(const float4*)&g_aggc[arow * C + k0 + q * 4];
        *(float4*)&sAc[lm][8 * q]     = make_float4(v.x, v.x, v.y, v.y);
        *(float4*)&sAc[lm][8 * q + 4] = make_float4(v.z, v.z, v.w, v.w);
        v = *(const float4*)&g_agge[arow * C + k0 + q * 4];
        *(float4*)&sAe[lm][8 * q]     = make_float4(v.x, v.x, v.y, v.y);
        *(float4*)&sAe[lm][8 * q + 4] = make_float4(v.z, v.z, v.w, v.w);
        v = *(const float4*)&X3[arow * C + k0 + q * 4];
        *(float4*)&sA3[lm][8 * q]     = make_float4(v.x, v.x, v.y, v.y);
        *(float4*)&sA3[lm][8 * q + 4] = make_float4(v.z, v.z, v.w, v.w);
        v = *(const float4*)&X4[arow * C + k0 + q * 4];
        *(float4*)&sA4[lm][8 * q]     = make_float4(v.x, v.x, v.y, v.y);
        *(float4*)&sA4[lm][8 * q + 4] = make_float4(v.z, v.z, v.w, v.w);
        *(float4*)&sBl[kr][cb]     = *(const float4*)&Wl[(k0 + kr) * C + cb];
        *(float4*)&sBl[kr][cb + 4] = *(const float4*)&Wl[(k0 + kr) * C + cb + 4];
        *(float4*)&sBr[kr][cb]     = *(const float4*)&Wr[(k0 + kr) * C + cb];
        *(float4*)&sBr[kr][cb + 4] = *(const float4*)&Wr[(k0 + kr) * C + cb + 4];
        __syncthreads();
        #pragma unroll
        for (int k = 0; k < 16; k++) {
            const u64* pl = (const u64*)&sBl[k][0];
            const u64* pr = (const u64*)&sBr[k][0];
            u64 bl[4], br[4];
            #pragma unroll
            for (int j = 0; j < 4; j++) { bl[j] = pl[tx + 16 * j]; br[j] = pr[tx + 16 * j]; }
            #pragma unroll
            for (int i = 0; i < 4; i++) {
                u64 a_c = *(const u64*)&sAc[(ty << 2) + i][2 * k];
                u64 a_e = *(const u64*)&sAe[(ty << 2) + i][2 * k];
                u64 a_3 = *(const u64*)&sA3[(ty << 2) + i][2 * k];
                u64 a_4 = *(const u64*)&sA4[(ty << 2) + i][2 * k];
                #pragma unroll
                for (int j = 0; j < 4; j++) {
                    ffma2(acc1[i][j], a_c, bl[j]);
                    ffma2(acc1[i][j], a_3, br[j]);
                    ffma2(acc2[i][j], a_e, bl[j]);
                    ffma2(acc2[i][j], a_4, br[j]);
                }
            }
        }
        __syncthreads();
    }
    #pragma unroll
    for (int i = 0; i < 4; i++) {
        int r = row0 + (ty << 2) + i;
        if (r < M) {
            #pragma unroll
            for (int j = 0; j < 4; j++) {
                int c0 = 2 * tx + 32 * j;
                float2 bb = *(const float2*)&bias[c0];
                float2 o1, o2;
                o1.x = lo32(acc1[i][j]) + bb.x;
                o1.y = hi32(acc1[i][j]) + bb.y;
                o2.x = lo32(acc2[i][j]) + bb.x;
                o2.y = hi32(acc2[i][j]) + bb.y;
                *(float2*)&g_x1[r * C + c0] = o1;
                *(float2*)&g_x2[r * C + c0] = o2;
            }
        }
    }
}

// ---------------- attention scores: s[r] = tanh(z_r@W1 + b1)@W2, r = node*4+branch ----------------
__global__ void score_kernel(const float* __restrict__ X3, const float* __restrict__ X4,
                             const float* __restrict__ W1, const float* __restrict__ b1,
                             const float* __restrict__ W2, int R) {
    __shared__ __align__(16) float sA[128][36];
    __shared__ __align__(16) float sB[16][64];
    int tid = threadIdx.x;
    int tx = tid & 7, ty = tid >> 3;          // tx: 8 col-pair groups (64 cols), ty: 32 row groups
    int row0 = blockIdx.x * 128;
    u64 acc[4][4];
    #pragma unroll
    for (int i = 0; i < 4; i++)
        #pragma unroll
        for (int j = 0; j < 4; j++) acc[i][j] = 0;

    int lm = tid >> 1, h = tid & 1;           // A loader: row lm, half h
    int r = row0 + lm; if (r >= R) r = R - 1;
    int branch = r & 3, node = r >> 2;
    const float* zrow;
    if (branch == 0)      zrow = g_x1 + (size_t)node * C;
    else if (branch == 1) zrow = g_x2 + (size_t)node * C;
    else if (branch == 2) zrow = X3 + (size_t)node * C;
    else                  zrow = X4 + (size_t)node * C;
    int kr = tid >> 4, cb = (tid & 15) * 4;   // B loader

    for (int k0 = 0; k0 < C; k0 += 16) {
        float4 v1 = *(const float4*)&zrow[k0 + 8 * h];
        float4 v2 = *(const float4*)&zrow[k0 + 8 * h + 4];
        *(float4*)&sA[lm][16 * h]      = make_float4(v1.x, v1.x, v1.y, v1.y);
        *(float4*)&sA[lm][16 * h + 4]  = make_float4(v1.z, v1.z, v1.w, v1.w);
        *(float4*)&sA[lm][16 * h + 8]  = make_float4(v2.x, v2.x, v2.y, v2.y);
        *(float4*)&sA[lm][16 * h + 12] = make_float4(v2.z, v2.z, v2.w, v2.w);
        *(float4*)&sB[kr][cb] = *(const float4*)&W1[(k0 + kr) * 64 + cb];
        __syncthreads();
        #pragma unroll
        for (int k = 0; k < 16; k++) {
            const u64* pb = (const u64*)&sB[k][0];
            u64 bl[4];
            #pragma unroll
            for (int j = 0; j < 4; j++) bl[j] = pb[tx + 8 * j];
            #pragma unroll
            for (int i = 0; i < 4; i++) {
                u64 a = *(const u64*)&sA[(ty << 2) + i][2 * k];
                #pragma unroll
                for (int j = 0; j < 4; j++) ffma2(acc[i][j], a, bl[j]);
            }
        }
        __syncthreads();
    }
    #pragma unroll
    for (int i = 0; i < 4; i++) {
        float s = 0.f;
        #pragma unroll
        for (int j = 0; j < 4; j++) {
            int c0 = 2 * tx + 16 * j;
            float2 bb = *(const float2*)&b1[c0];
            float2 w2 = *(const float2*)&W2[c0];
            s += tanhf(lo32(acc[i][j]) + bb.x) * w2.x;
            s += tanhf(hi32(acc[i][j]) + bb.y) * w2.y;
        }
        #pragma unroll
        for (int o = 4; o; o >>= 1) s += __shfl_xor_sync(0xffffffffu, s, o);
        if (tx == 0) {
            int rr = row0 + (ty << 2) + i;
            if (rr < R) g_scores[rr] = s;
        }
    }
}

// ---------------- softmax + weighted pooling ----------------
__global__ void pool_kernel(const float* __restrict__ X3, const float* __restrict__ X4,
                            float* __restrict__ emb, int N) {
    int node = blockIdx.x * 8 + (threadIdx.x >> 5);
    int lane = threadIdx.x & 31;
    if (node >= N) return;
    float s0 = g_scores[node * 4 + 0];
    float s1 = g_scores[node * 4 + 1];
    float s2 = g_scores[node * 4 + 2];
    float s3 = g_scores[node * 4 + 3];
    float m = fmaxf(fmaxf(s0, s1), fmaxf(s2, s3));
    float e0 = expf(s0 - m), e1 = expf(s1 - m), e2 = expf(s2 - m), e3 = expf(s3 - m);
    float inv = 1.0f / (e0 + e1 + e2 + e3);
    float b0 = e0 * inv, b1 = e1 * inv, b2 = e2 * inv, b3 = e3 * inv;
    float4 z1 = __ldg(&((const float4*)(g_x1 + (size_t)node * C))[lane]);
    float4 z2 = __ldg(&((const float4*)(g_x2 + (size_t)node * C))[lane]);
    float4 z3 = __ldg(&((const float4*)(X3 + (size_t)node * C))[lane]);
    float4 z4 = __ldg(&((const float4*)(X4 + (size_t)node * C))[lane]);
    float4 o;
    o.x = b0 * z1.x + b1 * z2.x + b2 * z3.x + b3 * z4.x;
    o.y = b0 * z1.y + b1 * z2.y + b2 * z3.y + b3 * z4.y;
    o.z = b0 * z1.z + b1 * z2.z + b2 * z3.z + b3 * z4.z;
    o.w = b0 * z1.w + b1 * z2.w + b2 * z3.w + b3 * z4.w;
    ((float4*)(emb + (size_t)node * C))[lane] = o;
}

// ---------------- launch ----------------
extern "C" void kernel_launch(void* const* d_in, const int* in_sizes, int n_in,
                              void* d_out, int out_size) {
    const float* x   = (const float*)d_in[0];
    const int*   row = (const int*)d_in[1];
    const int*   col = (const int*)d_in[2];
    const float* Wl0 = (const float*)d_in[3];
    const float* bl0 = (const float*)d_in[4];
    const float* Wr0 = (const float*)d_in[5];
    const float* Wl1 = (const float*)d_in[6];
    const float* bl1 = (const float*)d_in[7];
    const float* Wr1 = (const float*)d_in[8];
    const float* aW1 = (const float*)d_in[9];
    const float* ab1 = (const float*)d_in[10];
    const float* aW2 = (const float*)d_in[11];

    int N = in_sizes[0] / C;
    int E = in_sizes[1];

    float* emb = (float*)d_out;
    float* x3o = emb + (size_t)N * C;
    float* x4o = x3o + (size_t)N * C;

    int nb8 = (N + 7) / 8;
    int nbE = (E + 255) / 256;
    int nbM = (N + 63) / 64;
    int nbS = (4 * N + 127) / 128;

    zero_cnt_kernel<<<(N + 255) / 256, 256>>>(N);
    hist_kernel<<<nbE, 256>>>(row, E);
    scan_kernel<<<1, 1024>>>(N);
    fill_kernel<<<nbE, 256>>>(row, col, E);

    norm_kernel<<<nb8, 256>>>(x, N);
    edge1_kernel<<<nb8, 256>>>(x, N);
    layer0_kernel<<<nbM, 256>>>(x, Wl0, Wr0, bl0, x3o, x4o, N);

    norm_kernel<<<nb8, 256>>>(x3o, N);
    edge2_kernel<<<nb8, 256>>>(x3o, x4o, N);
    layer1_kernel<<<nbM, 256>>>(x3o, x4o, Wl1, Wr1, bl1, N);

    score_kernel<<<nbS, 256>>>(x3o, x4o, aW1, ab1, aW2, 4 * N);
    pool_kernel<<<nb8, 256>>>(x3o, x4o, emb, N);
}

// round 11
// speedup vs baseline: 1.4069x; 1.0017x over previous
#include <cuda_runtime.h>
#include <math.h>

typedef unsigned long long u64;

#define NMAX 50000
#define EMAX 800000
#define C 128

// ---------------- scratch (static __device__, no allocation) ----------------
__device__ int   g_cnt [NMAX];
__device__ int   g_fill[NMAX];
__device__ int   g_ptr [NMAX + 1];
__device__ int   g_ecol[EMAX];
__device__ float g_norm[NMAX];
__device__ float g_aggc[NMAX * C];
__device__ float g_agge[NMAX * C];
__device__ float g_x1  [NMAX * C];
__device__ float g_x2  [NMAX * C];
__device__ float g_scores[NMAX * 4];

// ---------------- packed fp32x2 helpers (SASS FFMA2) ----------------
__device__ __forceinline__ void ffma2(u64& d, u64 a, u64 b) {
    asm("fma.rn.f32x2 %0, %1, %2, %0;" : "+l"(d) : "l"(a), "l"(b));
}
__device__ __forceinline__ float lo32(u64 v) { return __uint_as_float((unsigned)v); }
__device__ __forceinline__ float hi32(u64 v) { return __uint_as_float((unsigned)(v >> 32)); }

// ---------------- CSR build ----------------
__global__ void zero_cnt_kernel(int N) {
    int i = blockIdx.x * blockDim.x + threadIdx.x;
    if (i < N) g_cnt[i] = 0;
}

__global__ void hist_kernel(const int* __restrict__ row, int E) {
    int i = blockIdx.x * blockDim.x + threadIdx.x;
    if (i < E) atomicAdd(&g_cnt[row[i]], 1);
}

__global__ void scan_kernel(int N) {
    __shared__ int sums[1024];
    int t = threadIdx.x;
    int chunk = (N + 1023) >> 10;
    int start = t * chunk;
    int end = min(start + chunk, N);
    int s = 0;
    for (int i = start; i < end; i++) s += g_cnt[i];
    sums[t] = s;
    __syncthreads();
    for (int off = 1; off < 1024; off <<= 1) {
        int v = (t >= off) ? sums[t - off] : 0;
        __syncthreads();
        sums[t] += v;
        __syncthreads();
    }
    int base = sums[t] - s;
    for (int i = start; i < end; i++) {
        g_ptr[i]  = base;
        g_fill[i] = base;
        base += g_cnt[i];
    }
    if (t == 0) g_ptr[N] = sums[1023];
}

__global__ void fill_kernel(const int* __restrict__ row, const int* __restrict__ col, int E) {
    int i = blockIdx.x * blockDim.x + threadIdx.x;
    if (i < E) {
        int r = row[i];
        int p = atomicAdd(&g_fill[r], 1);
        g_ecol[p] = col[i];
    }
}

// ---------------- per-node L2 norms ----------------
__global__ void norm_kernel(const float* __restrict__ X, int N) {
    int node = blockIdx.x * 8 + (threadIdx.x >> 5);
    int lane = threadIdx.x & 31;
    if (node >= N) return;
    float4 v = ((const float4*)X)[node * 32 + lane];
    float s = v.x * v.x + v.y * v.y + v.z * v.z + v.w * v.w;
    #pragma unroll
    for (int o = 16; o; o >>= 1) s += __shfl_xor_sync(0xffffffffu, s, o);
    if (lane == 0) g_norm[node] = sqrtf(s);
}

// ---------------- edge pass 1: cos + eud on x, fused gather-aggregate ----------------
__global__ void edge1_kernel(const float* __restrict__ X, int N) {
    int node = blockIdx.x * 8 + (threadIdx.x >> 5);
    int lane = threadIdx.x & 31;
    if (node >= N) return;
    const float4* X4 = (const float4*)X;
    float4 xi = X4[node * 32 + lane];
    float ni = g_norm[node];
    int s = g_ptr[node], e = g_ptr[node + 1];
    float4 ac = make_float4(0.f, 0.f, 0.f, 0.f);
    float4 ae = make_float4(0.f, 0.f, 0.f, 0.f);
    int cNext = (s < e) ? __ldg(&g_ecol[s]) : 0;
    for (int j = s; j < e; j++) {
        int c = cNext;
        if (j + 1 < e) cNext = __ldg(&g_ecol[j + 1]);
        float4 xc = __ldg(&X4[c * 32 + lane]);
        float nc = __ldg(&g_norm[c]);
        float d = xi.x * xc.x + xi.y * xc.y + xi.z * xc.z + xi.w * xc.w;
        float ux = xi.x - xc.x + 1e-6f;
        float uy = xi.y - xc.y + 1e-6f;
        float uz = xi.z - xc.z + 1e-6f;
        float uw = xi.w - xc.w + 1e-6f;
        float u = ux * ux + uy * uy + uz * uz + uw * uw;
        #pragma unroll
        for (int o = 16; o; o >>= 1) {
            d += __shfl_xor_sync(0xffffffffu, d, o);
            u += __shfl_xor_sync(0xffffffffu, u, o);
        }
        float ecos = d / fmaxf(ni * nc, 1e-8f);
        float eeud = sqrtf(u);
        ac.x += ecos * xc.x; ac.y += ecos * xc.y; ac.z += ecos * xc.z; ac.w += ecos * xc.w;
        ae.x += eeud * xc.x; ae.y += eeud * xc.y; ae.z += eeud * xc.z; ae.w += eeud * xc.w;
    }
    float inv = 1.0f / fmaxf((float)(e - s), 1.0f);
    ac.x *= inv; ac.y *= inv; ac.z *= inv; ac.w *= inv;
    ae.x *= inv; ae.y *= inv; ae.z *= inv; ae.w *= inv;
    ((float4*)g_aggc)[node * 32 + lane] = ac;
    ((float4*)g_agge)[node * 32 + lane] = ae;
}

// ---------------- edge pass 2: cos on x3, eud on x4 ----------------
__global__ void edge2_kernel(const float* __restrict__ X3, const float* __restrict__ X4, int N) {
    int node = blockIdx.x * 8 + (threadIdx.x >> 5);
    int lane = threadIdx.x & 31;
    if (node >= N) return;
    const float4* A4 = (const float4*)X3;
    const float4* B4 = (const float4*)X4;
    float4 x3i = A4[node * 32 + lane];
    float4 x4i = B4[node * 32 + lane];
    float n3 = g_norm[node];
    int s = g_ptr[node], e = g_ptr[node + 1];
    float4 ac = make_float4(0.f, 0.f, 0.f, 0.f);
    float4 ae = make_float4(0.f, 0.f, 0.f, 0.f);
    int cNext = (s < e) ? __ldg(&g_ecol[s]) : 0;
    for (int j = s; j < e; j++) {
        int c = cNext;
        if (j + 1 < e) cNext = __ldg(&g_ecol[j + 1]);
        float4 xc3 = __ldg(&A4[c * 32 + lane]);
        float4 xc4 = __ldg(&B4[c * 32 + lane]);
        float nc = __ldg(&g_norm[c]);
        float d = x3i.x * xc3.x + x3i.y * xc3.y + x3i.z * xc3.z + x3i.w * xc3.w;
        float ux = x4i.x - xc4.x + 1e-6f;
        float uy = x4i.y - xc4.y + 1e-6f;
        float uz = x4i.z - xc4.z + 1e-6f;
        float uw = x4i.w - xc4.w + 1e-6f;
        float u = ux * ux + uy * uy + uz * uz + uw * uw;
        #pragma unroll
        for (int o = 16; o; o >>= 1) {
            d += __shfl_xor_sync(0xffffffffu, d, o);
            u += __shfl_xor_sync(0xffffffffu, u, o);
        }
        float ecos = d / fmaxf(n3 * nc, 1e-8f);
        float eeud = sqrtf(u);
        ac.x += ecos * xc3.x; ac.y += ecos * xc3.y; ac.z += ecos * xc3.z; ac.w += ecos * xc3.w;
        ae.x += eeud * xc4.x; ae.y += eeud * xc4.y; ae.z += eeud * xc4.z; ae.w += eeud * xc4.w;
    }
    float inv = 1.0f / fmaxf((float)(e - s), 1.0f);
    ac.x *= inv; ac.y *= inv; ac.z *= inv; ac.w *= inv;
    ae.x *= inv; ae.y *= inv; ae.z *= inv; ae.w *= inv;
    ((float4*)g_aggc)[node * 32 + lane] = ac;
    ((float4*)g_agge)[node * 32 + lane] = ae;
}

// ==================== GEMM kernels: 64/128 rows x 128/64 cols, strided col pairs ====================
// Thread (tx,ty): owns rows ty*4..+3, col pairs {2tx+32j} (layer) / {2tx+16j} (score).
// B smem reads: LDS64 at u64-index tx+16j -> bank 2tx, conflict-free broadcast.
// A smem: duplicated {a,a} pairs, row stride 36 floats, broadcast reads.

// ---------------- layer 0: x3 = relu(aggc@Wl + x@Wr + b), x4 = relu(agge@Wl + x@Wr + b) ----------------
__global__ void layer0_kernel(const float* __restrict__ X,
                              const float* __restrict__ Wl, const float* __restrict__ Wr,
                              const float* __restrict__ bias,
                              float* __restrict__ O3, float* __restrict__ O4, int M) {
    __shared__ __align__(16) float sAc[64][36], sAe[64][36], sAx[64][36];
    __shared__ __align__(16) float sBl[16][128], sBr[16][128];
    int tid = threadIdx.x;
    int tx = tid & 15, ty = tid >> 4;        // tx: 16 col-pair groups, ty: 16 row groups
    int row0 = blockIdx.x * 64;
    u64 accC[4][4], accE[4][4], accX[4][4];
    #pragma unroll
    for (int i = 0; i < 4; i++)
        #pragma unroll
        for (int j = 0; j < 4; j++) { accC[i][j] = 0; accE[i][j] = 0; accX[i][j] = 0; }

    int lm = tid >> 2, q = tid & 3;          // A loader: row lm, quarter q
    int arow = row0 + lm; if (arow >= M) arow = M - 1;
    int kr = tid >> 4, cb = (tid & 15) * 8;  // B loader

    for (int k0 = 0; k0 < C; k0 += 16) {
        float4 v;
        v = *(const float4*)&g_aggc[arow * C + k0 + q * 4];
        *(float4*)&sAc[lm][8 * q]     = make_float4(v.x, v.x, v.y, v.y);
        *(float4*)&sAc[lm][8 * q + 4] = make_float4(v.z, v.z, v.w, v.w);
        v = *(const float4*)&g_agge[arow * C + k0 + q * 4];
        *(float4*)&sAe[lm][8 * q]     = make_float4(v.x, v.x, v.y, v.y);
        *(float4*)&sAe[lm][8 * q + 4] = make_float4(v.z, v.z, v.w, v.w);
        v = *(const float4*)&X[arow * C + k0 + q * 4];
        *(float4*)&sAx[lm][8 * q]     = make_float4(v.x, v.x, v.y, v.y);
        *(float4*)&sAx[lm][8 * q + 4] = make_float4(v.z, v.z, v.w, v.w);
        *(float4*)&sBl[kr][cb]     = *(const float4*)&Wl[(k0 + kr) * C + cb];
        *(float4*)&sBl[kr][cb + 4] = *(const float4*)&Wl[(k0 + kr) * C + cb + 4];
        *(float4*)&sBr[kr][cb]     = *(const float4*)&Wr[(k0 + kr) * C + cb];
        *(float4*)&sBr[kr][cb + 4] = *(const float4*)&Wr[(k0 + kr) * C + cb + 4];
        __syncthreads();
        #pragma unroll
        for (int k = 0; k < 16; k++) {
            const u64* pl = (const u64*)&sBl[k][0];
            const u64* pr = (const u64*)&sBr[k][0];
            u64 bl[4], br[4];
            #pragma unroll
            for (int j = 0; j < 4; j++) { bl[j] = pl[tx + 16 * j]; br[j] = pr[tx + 16 * j]; }
            #pragma unroll
            for (int i = 0; i < 4; i++) {
                u64 a_c = *(const u64*)&sAc[(ty << 2) + i][2 * k];
                u64 a_e = *(const u64*)&sAe[(ty << 2) + i][2 * k];
                u64 a_x = *(const u64*)&sAx[(ty << 2) + i][2 * k];
                #pragma unroll
                for (int j = 0; j < 4; j++) {
                    ffma2(accC[i][j], a_c, bl[j]);
                    ffma2(accE[i][j], a_e, bl[j]);
                    ffma2(accX[i][j], a_x, br[j]);
                }
            }
        }
        __syncthreads();
    }
    #pragma unroll
    for (int i = 0; i < 4; i++) {
        int r = row0 + (ty << 2) + i;
        if (r < M) {
            #pragma unroll
            for (int j = 0; j < 4; j++) {
                int c0 = 2 * tx + 32 * j;
                float2 bb = *(const float2*)&bias[c0];
                float2 o3, o4;
                float xlo = lo32(accX[i][j]), xhi = hi32(accX[i][j]);
                o3.x = fmaxf(lo32(accC[i][j]) + xlo + bb.x, 0.f);
                o3.y = fmaxf(hi32(accC[i][j]) + xhi + bb.y, 0.f);
                o4.x = fmaxf(lo32(accE[i][j]) + xlo + bb.x, 0.f);
                o4.y = fmaxf(hi32(accE[i][j]) + xhi + bb.y, 0.f);
                *(float2*)&O3[r * C + c0] = o3;
                *(float2*)&O4[r * C + c0] = o4;
            }
        }
    }
}

// ---------------- layer 1: x1 = aggc@Wl + x3@Wr + b ; x2 = agge@Wl + x4@Wr + b ----------------
__global__ void layer1_kernel(const float* __restrict__ X3, const float* __restrict__ X4,
                              const float* __restrict__ Wl, const float* __restrict__ Wr,
                              const float* __restrict__ bias, int M) {
    __shared__ __align__(16) float sAc[64][36], sAe[64][36], sA3[64][36], sA4[64][36];
    __shared__ __align__(16) float sBl[16][128], sBr[16][128];
    int tid = threadIdx.x;
    int tx = tid & 15, ty = tid >> 4;
    int row0 = blockIdx.x * 64;
    u64 acc1[4][4], acc2[4][4];
    #pragma unroll
    for (int i = 0; i < 4; i++)
        #pragma unroll
        for (int j = 0; j < 4; j++) { acc1[i][j] = 0; acc2[i][j] = 0; }

    int lm = tid >> 2, q = tid & 3;
    int arow = row0 + lm; if (arow >= M) arow = M - 1;
    int kr = tid >> 4, cb = (tid & 15) * 8;

    for (int k0 = 0; k0 < C; k0 += 16) {
        float4 v;
        v = *(const float4*)&g_aggc[arow * C + k0 + q * 4];
        *(float4*)&sAc[lm][8 * q]     = make_float4(v.x, v.x, v.y, v.y);
        *(float4*)&sAc[lm][8 * q + 4] = make_float4(v.z, v.z, v.w, v.w);
        v = *(const float4*)&g_agge[arow * C + k0 + q * 4];
        *(float4*)&sAe[lm][8 * q]     = make_float4(v.x, v.x, v.y, v.y);
        *(float4*)&sAe[lm][8 * q + 4] = make_float4(v.z, v.z, v.w, v.w);
        v = *(const float4*)&X3[arow * C + k0 + q * 4];
        *(float4*)&sA3[lm][8 * q]     = make_float4(v.x, v.x, v.y, v.y);
        *(float4*)&sA3[lm][8 * q + 4] = make_float4(v.z, v.z, v.w, v.w);
        v = *(const float4*)&X4[arow * C + k0 + q * 4];
        *(float4*)&sA4[lm][8 * q]     = make_float4(v.x, v.x, v.y, v.y);
        *(float4*)&sA4[lm][8 * q + 4] = make_float4(v.z, v.z, v.w, v.w);
        *(float4*)&sBl[kr][cb]     = *(const float4*)&Wl[(k0 + kr) * C + cb];
        *(float4*)&sBl[kr][cb + 4] = *(const float4*)&Wl[(k0 + kr) * C + cb + 4];
        *(float4*)&sBr[kr][cb]     = *(const float4*)&Wr[(k0 + kr) * C + cb];
        *(float4*)&sBr[kr][cb + 4] = *(const float4*)&Wr[(k0 + kr) * C + cb + 4];
        __syncthreads();
        #pragma unroll
        for (int k = 0; k < 16; k++) {
            const u64* pl = (const u64*)&sBl[k][0];
            const u64* pr = (const u64*)&sBr[k][0];
            u64 bl[4], br[4];
            #pragma unroll
            for (int j = 0; j < 4; j++) { bl[j] = pl[tx + 16 * j]; br[j] = pr[tx + 16 * j]; }
            #pragma unroll
            for (int i = 0; i < 4; i++) {
                u64 a_c = *(const u64*)&sAc[(ty << 2) + i][2 * k];
                u64 a_e = *(const u64*)&sAe[(ty << 2) + i][2 * k];
                u64 a_3 = *(const u64*)&sA3[(ty << 2) + i][2 * k];
                u64 a_4 = *(const u64*)&sA4[(ty << 2) + i][2 * k];
                #pragma unroll
                for (int j = 0; j < 4; j++) {
                    ffma2(acc1[i][j], a_c, bl[j]);
                    ffma2(acc1[i][j], a_3, br[j]);
                    ffma2(acc2[i][j], a_e, bl[j]);
                    ffma2(acc2[i][j], a_4, br[j]);
                }
            }
        }
        __syncthreads();
    }
    #pragma unroll
    for (int i = 0; i < 4; i++) {
        int r = row0 + (ty << 2) + i;
        if (r < M) {
            #pragma unroll
            for (int j = 0; j < 4; j++) {
                int c0 = 2 * tx + 32 * j;
                float2 bb = *(const float2*)&bias[c0];
                float2 o1, o2;
                o1.x = lo32(acc1[i][j]) + bb.x;
                o1.y = hi32(acc1[i][j]) + bb.y;
                o2.x = lo32(acc2[i][j]) + bb.x;
                o2.y = hi32(acc2[i][j]) + bb.y;
                *(float2*)&g_x1[r * C + c0] = o1;
                *(float2*)&g_x2[r * C + c0] = o2;
            }
        }
    }
}

// ---------------- attention scores: s[r] = tanh(z_r@W1 + b1)@W2, r = node*4+branch ----------------
__global__ void score_kernel(const float* __restrict__ X3, const float* __restrict__ X4,
                             const float* __restrict__ W1, const float* __restrict__ b1,
                             const float* __restrict__ W2, int R) {
    __shared__ __align__(16) float sA[128][36];
    __shared__ __align__(16) float sB[16][64];
    int tid = threadIdx.x;
    int tx = tid & 7, ty = tid >> 3;          // tx: 8 col-pair groups (64 cols), ty: 32 row groups
    int row0 = blockIdx.x * 128;
    u64 acc[4][4];
    #pragma unroll
    for (int i = 0; i < 4; i++)
        #pragma unroll
        for (int j = 0; j < 4; j++) acc[i][j] = 0;

    int lm = tid >> 1, h = tid & 1;           // A loader: row lm, half h
    int r = row0 + lm; if (r >= R) r = R - 1;
    int branch = r & 3, node = r >> 2;
    const float* zrow;
    if (branch == 0)      zrow = g_x1 + (size_t)node * C;
    else if (branch == 1) zrow = g_x2 + (size_t)node * C;
    else if (branch == 2) zrow = X3 + (size_t)node * C;
    else                  zrow = X4 + (size_t)node * C;
    int kr = tid >> 4, cb = (tid & 15) * 4;   // B loader

    for (int k0 = 0; k0 < C; k0 += 16) {
        float4 v1 = *(const float4*)&zrow[k0 + 8 * h];
        float4 v2 = *(const float4*)&zrow[k0 + 8 * h + 4];
        *(float4*)&sA[lm][16 * h]      = make_float4(v1.x, v1.x, v1.y, v1.y);
        *(float4*)&sA[lm][16 * h + 4]  = make_float4(v1.z, v1.z, v1.w, v1.w);
        *(float4*)&sA[lm][16 * h + 8]  = make_float4(v2.x, v2.x, v2.y, v2.y);
        *(float4*)&sA[lm][16 * h + 12] = make_float4(v2.z, v2.z, v2.w, v2.w);
        *(float4*)&sB[kr][cb] = *(const float4*)&W1[(k0 + kr) * 64 + cb];
        __syncthreads();
        #pragma unroll
        for (int k = 0; k < 16; k++) {
            const u64* pb = (const u64*)&sB[k][0];
            u64 bl[4];
            #pragma unroll
            for (int j = 0; j < 4; j++) bl[j] = pb[tx + 8 * j];
            #pragma unroll
            for (int i = 0; i < 4; i++) {
                u64 a = *(const u64*)&sA[(ty << 2) + i][2 * k];
                #pragma unroll
                for (int j = 0; j < 4; j++) ffma2(acc[i][j], a, bl[j]);
            }
        }
        __syncthreads();
    }
    #pragma unroll
    for (int i = 0; i < 4; i++) {
        float s = 0.f;
        #pragma unroll
        for (int j = 0; j < 4; j++) {
            int c0 = 2 * tx + 16 * j;
            float2 bb = *(const float2*)&b1[c0];
            float2 w2 = *(const float2*)&W2[c0];
            s += tanhf(lo32(acc[i][j]) + bb.x) * w2.x;
            s += tanhf(hi32(acc[i][j]) + bb.y) * w2.y;
        }
        #pragma unroll
        for (int o = 4; o; o >>= 1) s += __shfl_xor_sync(0xffffffffu, s, o);
        if (tx == 0) {
            int rr = row0 + (ty << 2) + i;
            if (rr < R) g_scores[rr] = s;
        }
    }
}

// ---------------- softmax + weighted pooling ----------------
__global__ void pool_kernel(const float* __restrict__ X3, const float* __restrict__ X4,
                            float* __restrict__ emb, int N) {
    int node = blockIdx.x * 8 + (threadIdx.x >> 5);
    int lane = threadIdx.x & 31;
    if (node >= N) return;
    float s0 = g_scores[node * 4 + 0];
    float s1 = g_scores[node * 4 + 1];
    float s2 = g_scores[node * 4 + 2];
    float s3 = g_scores[node * 4 + 3];
    float m = fmaxf(fmaxf(s0, s1), fmaxf(s2, s3));
    float e0 = expf(s0 - m), e1 = expf(s1 - m), e2 = expf(s2 - m), e3 = expf(s3 - m);
    float inv = 1.0f / (e0 + e1 + e2 + e3);
    float b0 = e0 * inv, b1 = e1 * inv, b2 = e2 * inv, b3 = e3 * inv;
    float4 z1 = __ldg(&((const float4*)(g_x1 + (size_t)node * C))[lane]);
    float4 z2 = __ldg(&((const float4*)(g_x2 + (size_t)node * C))[lane]);
    float4 z3 = __ldg(&((const float4*)(X3 + (size_t)node * C))[lane]);
    float4 z4 = __ldg(&((const float4*)(X4 + (size_t)node * C))[lane]);
    float4 o;
    o.x = b0 * z1.x + b1 * z2.x + b2 * z3.x + b3 * z4.x;
    o.y = b0 * z1.y + b1 * z2.y + b2 * z3.y + b3 * z4.y;
    o.z = b0 * z1.z + b1 * z2.z + b2 * z3.z + b3 * z4.z;
    o.w = b0 * z1.w + b1 * z2.w + b2 * z3.w + b3 * z4.w;
    ((float4*)(emb + (size_t)node * C))[lane] = o;
}

// ---------------- launch ----------------
extern "C" void kernel_launch(void* const* d_in, const int* in_sizes, int n_in,
                              void* d_out, int out_size) {
    const float* x   = (const float*)d_in[0];
    const int*   row = (const int*)d_in[1];
    const int*   col = (const int*)d_in[2];
    const float* Wl0 = (const float*)d_in[3];
    const float* bl0 = (const float*)d_in[4];
    const float* Wr0 = (const float*)d_in[5];
    const float* Wl1 = (const float*)d_in[6];
    const float* bl1 = (const float*)d_in[7];
    const float* Wr1 = (const float*)d_in[8];
    const float* aW1 = (const float*)d_in[9];
    const float* ab1 = (const float*)d_in[10];
    const float* aW2 = (const float*)d_in[11];

    int N = in_sizes[0] / C;
    int E = in_sizes[1];

    float* emb = (float*)d_out;
    float* x3o = emb + (size_t)N * C;
    float* x4o = x3o + (size_t)N * C;

    int nb8 = (N + 7) / 8;
    int nbE = (E + 255) / 256;
    int nbM = (N + 63) / 64;
    int nbS = (4 * N + 127) / 128;

    zero_cnt_kernel<<<(N + 255) / 256, 256>>>(N);
    hist_kernel<<<nbE, 256>>>(row, E);
    scan_kernel<<<1, 1024>>>(N);
    fill_kernel<<<nbE, 256>>>(row, col, E);

    norm_kernel<<<nb8, 256>>>(x, N);
    edge1_kernel<<<nb8, 256>>>(x, N);
    layer0_kernel<<<nbM, 256>>>(x, Wl0, Wr0, bl0, x3o, x4o, N);

    norm_kernel<<<nb8, 256>>>(x3o, N);
    edge2_kernel<<<nb8, 256>>>(x3o, x4o, N);
    layer1_kernel<<<nbM, 256>>>(x3o, x4o, Wl1, Wr1, bl1, N);

    score_kernel<<<nbS, 256>>>(x3o, x4o, aW1, ab1, aW2, 4 * N);
    pool_kernel<<<nb8, 256>>>(x3o, x4o, emb, N);
}